// round 2
// baseline (speedup 1.0000x reference)
#include <cuda_runtime.h>
#include <math.h>

#define BB 16
#define CC 64
#define NN 4096
#define KK 128
#define MM 257
#define TEMBD 256
#define HH 128
#define MP 288
#define NSPLIT 16
#define PI_F 3.14159265358979323846f

// ---------------- device scratch (no allocations allowed) ----------------
__device__ float g_kappa[MP];
__device__ float g_invw[MP];
__device__ float g_gate[BB*MM];
__device__ float g_tvec[BB*CC];
__device__ int   g_midx[MP];
__device__ int   g_Mact;
__device__ float g_kcpt[MP];
__device__ float g_ccpt[MP];
__device__ float g_iwcpt[MP];
__device__ float g_Xr[(size_t)NSPLIT*BB*CC*MP];
__device__ float g_Xi[(size_t)NSPLIT*BB*CC*MP];
__device__ float g_Yr[(size_t)BB*CC*MP];
__device__ float g_Yi[(size_t)BB*CC*MP];

__device__ __forceinline__ float sigmoidf_(float x){ return 1.f/(1.f+expf(-x)); }
__device__ __forceinline__ float softplusf_(float x){ return log1pf(expf(x)); }

// ---------------- kernel 0: all the small math ----------------
__global__ void k_setup(const float* __restrict__ temb,
                        const float* __restrict__ kappa_raw,
                        const float* __restrict__ gabor_c,
                        const float* __restrict__ gabor_omega_raw,
                        const float* __restrict__ tproj_w,
                        const float* __restrict__ tproj_b,
                        const float* __restrict__ mlp_w1,
                        const float* __restrict__ mlp_b1,
                        const float* __restrict__ mlp_w2,
                        const float* __restrict__ mlp_b2,
                        const float* __restrict__ tau0p,
                        const float* __restrict__ tau1p,
                        const float* __restrict__ alphap,
                        const float* __restrict__ glowp,
                        const float* __restrict__ gmidp,
                        const float* __restrict__ ghighp)
{
    __shared__ float kpos[KK];
    __shared__ float hid[BB*HH];
    __shared__ float tau[BB];
    __shared__ float th1s, th2s;
    __shared__ float gmax[MM];
    int tid = threadIdx.x;

    if (tid < KK) kpos[tid] = softplusf_(kappa_raw[tid]);
    __syncthreads();
    if (tid == 0) {
        float s = 0.f;
        for (int k = 0; k < KK; k++) { s += kpos[k]; kpos[k] = s; }
        // quantile(|kappa|, q): sorted |kappa| = [0, kpos0,kpos0, kpos1,kpos1, ...]
        // q=0.4: h=0.4*256=102.4 -> s[102]=kpos[50], s[103]=kpos[51]
        // q=0.8: h=204.8 -> s[204]=kpos[101], s[205]=kpos[102]
        th1s = kpos[50]  + 0.4f*(kpos[51] - kpos[50]);
        th2s = kpos[101] + 0.8f*(kpos[102] - kpos[101]);
    }
    __syncthreads();

    for (int m = tid; m < MM; m += blockDim.x) {
        float kv = (m < KK) ? -kpos[KK-1-m] : ((m == KK) ? 0.f : kpos[m-KK-1]);
        g_kappa[m] = kv;
        float om = fmaxf(softplusf_(gabor_omega_raw[m]), 1e-6f);
        g_invw[m] = 1.f/om;
    }

    // MLP hidden: hid = silu(temb @ W1^T + b1)
    for (int i = tid; i < BB*HH; i += blockDim.x) {
        int b = i / HH, h = i % HH;
        float acc = mlp_b1[h];
        const float* te = temb + b*TEMBD;
        const float* w  = mlp_w1 + h*TEMBD;
        for (int t = 0; t < TEMBD; t++) acc = fmaf(te[t], w[t], acc);
        hid[i] = acc * sigmoidf_(acc);
    }
    __syncthreads();
    if (tid < BB) {
        float acc = mlp_b2[0];
        for (int h = 0; h < HH; h++) acc = fmaf(hid[tid*HH+h], mlp_w2[h], acc);
        tau[tid] = tau0p[0] + softplusf_(tau1p[0]) * tanhf(acc);
    }

    // tvec[b][c] = silu(temb[b]) . tproj_w[c] + tproj_b[c]
    for (int i = tid; i < BB*CC; i += blockDim.x) {
        int b = i / CC, c = i % CC;
        float acc = tproj_b[c];
        const float* te = temb + b*TEMBD;
        const float* w  = tproj_w + c*TEMBD;
        for (int t = 0; t < TEMBD; t++) {
            float e = te[t];
            acc = fmaf(e * sigmoidf_(e), w[t], acc);
        }
        g_tvec[i] = acc;
    }
    __syncthreads();

    float alpha = softplusf_(alphap[0]) + 1e-12f;
    float gl = sigmoidf_(glowp[0]);
    float gm = sigmoidf_(gmidp[0]);
    float gh = sigmoidf_(ghighp[0]);
    for (int m = tid; m < MM; m += blockDim.x) {
        float ka = fabsf(g_kappa[m]);
        float bandv = (ka <= th1s) ? gl : ((ka <= th2s) ? gm : gh);
        float mx = 0.f;
        for (int b = 0; b < BB; b++) {
            float g = bandv * sigmoidf_(alpha*(tau[b]-ka));
            g_gate[b*MM+m] = g;
            mx = fmaxf(mx, g);
        }
        gmax[m] = mx;
    }
    __syncthreads();

    if (tid == 0) {
        int cnt = 0;
        for (int m = 0; m < MM; m++) {
            if (gmax[m] > 1e-7f) {
                g_midx[cnt]  = m;
                g_kcpt[cnt]  = g_kappa[m];
                g_ccpt[cnt]  = gabor_c[m];
                g_iwcpt[cnt] = g_invw[m];
                cnt++;
            }
        }
        g_Mact = cnt;
        for (int j = cnt; j < MP; j++) { g_kcpt[j]=0.f; g_ccpt[j]=0.f; g_iwcpt[j]=1.f; g_midx[j]=0; }
    }
}

// ---------------- kernel 1: analysis (fused basis + GEMM, n-split partials) ----------------
__global__ void __launch_bounds__(256) k_analysis(const float* __restrict__ x_feat,
                                                  const float* __restrict__ z)
{
    int mt = blockIdx.x;
    int nsplit = blockIdx.y;
    int b = blockIdx.z;
    int Mact = g_Mact;
    int m0 = mt * 32;
    if (m0 >= Mact) return;
    int mcnt = min(32, Mact - m0);

    __shared__ float km[32], cm[32], iw[32];
    __shared__ float zsm[64], zp[64];
    __shared__ float cwsm[64][32], swsm[64][32];
    __shared__ float xsm[64][65];

    int tid = threadIdx.x;
    if (tid < 32) {
        int j = m0 + tid;
        km[tid] = g_kcpt[j];
        cm[tid] = g_ccpt[j];
        iw[tid] = g_iwcpt[j];
    }
    int mg = tid & 7, cg = tid >> 3;      // thread owns c={cg, cg+32}, m={4mg..4mg+3}
    float ar0[4]={0,0,0,0}, ar1[4]={0,0,0,0};
    float ai0[4]={0,0,0,0}, ai1[4]={0,0,0,0};
    int c_tid = tid >> 2, q_tid = tid & 3; // loader mapping
    float tvc = g_tvec[b*CC + c_tid];
    const float* zb = z + b*NN;

    for (int nc = 0; nc < 4; nc++) {
        int n0 = nsplit*256 + nc*64;
        __syncthreads();
        if (tid < 64) {
            float zv = zb[n0 + tid];
            zsm[tid] = zv;
            zp[tid]  = zv * (1.f/PI_F);
        }
        {
            const float4* xg = (const float4*)(x_feat + ((size_t)(b*CC + c_tid))*NN + n0);
            #pragma unroll
            for (int k2 = 0; k2 < 4; k2++) {
                float4 v = xg[q_tid*4 + k2];
                int nn = (q_tid*4 + k2)*4;
                xsm[c_tid][nn+0] = v.x + tvc;
                xsm[c_tid][nn+1] = v.y + tvc;
                xsm[c_tid][nn+2] = v.z + tvc;
                xsm[c_tid][nn+3] = v.w + tvc;
            }
        }
        __syncthreads();
        #pragma unroll
        for (int e = 0; e < 8; e++) {
            int idx = e*256 + tid;
            int nn = idx >> 5, mm = idx & 31;
            float s, c;
            sincosf(zsm[nn]*km[mm], &s, &c);
            float d = (zp[nn]-cm[mm])*iw[mm];
            float w = expf(-0.5f*d*d);
            cwsm[nn][mm] = c*w;
            swsm[nn][mm] = s*w;
        }
        __syncthreads();
        #pragma unroll 4
        for (int nn = 0; nn < 64; nn++) {
            float xa = xsm[cg][nn];
            float xb = xsm[cg+32][nn];
            float4 cv = *(const float4*)&cwsm[nn][mg*4];
            float4 sv = *(const float4*)&swsm[nn][mg*4];
            float cva[4] = {cv.x, cv.y, cv.z, cv.w};
            float sva[4] = {sv.x, sv.y, sv.z, sv.w};
            #pragma unroll
            for (int k = 0; k < 4; k++) {
                ar0[k] = fmaf(xa, cva[k], ar0[k]);
                ai0[k] = fmaf(xa, sva[k], ai0[k]);
                ar1[k] = fmaf(xb, cva[k], ar1[k]);
                ai1[k] = fmaf(xb, sva[k], ai1[k]);
            }
        }
    }

    size_t base0 = ((size_t)(nsplit*BB + b)*CC + cg     )*MP + m0 + mg*4;
    size_t base1 = ((size_t)(nsplit*BB + b)*CC + cg + 32)*MP + m0 + mg*4;
    #pragma unroll
    for (int k = 0; k < 4; k++) {
        if (mg*4 + k < mcnt) {
            g_Xr[base0+k] = ar0[k]; g_Xi[base0+k] = ai0[k];
            g_Xr[base1+k] = ar1[k]; g_Xi[base1+k] = ai1[k];
        }
    }
}

// ---------------- kernel 2: combine splits, gate, complex weight ----------------
__global__ void k_comb(const float* __restrict__ wr, const float* __restrict__ wi)
{
    int bc = blockIdx.x;
    int b = bc / CC, c = bc % CC;
    int j = threadIdx.x;
    if (j >= g_Mact) return;
    int m = g_midx[j];
    float xr = 0.f, xi = 0.f;
    for (int ns = 0; ns < NSPLIT; ns++) {
        size_t idx = ((size_t)(ns*BB + b)*CC + c)*MP + j;
        xr += g_Xr[idx];
        xi += g_Xi[idx];
    }
    xr *=  (1.f/(float)NN);
    xi *= -(1.f/(float)NN);
    float g = g_gate[b*MM+m];
    float wrv = wr[c*MM+m], wiv = wi[c*MM+m];
    size_t o = ((size_t)b*CC + c)*MP + j;
    g_Yr[o] = g*(xr*wrv - xi*wiv);
    g_Yi[o] = g*(xr*wiv + xi*wrv);
}

// ---------------- kernel 3: synthesis (fused basis + GEMM) ----------------
__global__ void __launch_bounds__(256) k_synth(const float* __restrict__ z,
                                               const float* __restrict__ bias,
                                               float* __restrict__ out)
{
    int nt = blockIdx.x, b = blockIdx.y;
    int n0 = nt*64;
    __shared__ float zsm[64], zp[64];
    __shared__ float yr[32][68], yi[32][68];   // [j][c], padded, rows 16B-aligned
    __shared__ float cw[32][68], sw[32][68];   // [j][n]
    int tid = threadIdx.x;
    if (tid < 64) {
        float zv = z[b*NN + n0 + tid];
        zsm[tid] = zv;
        zp[tid]  = zv*(1.f/PI_F);
    }
    int ci = tid >> 4, ni = tid & 15;          // thread owns c=4ci..+3, n=4ni..+3
    float acc[4][4];
    #pragma unroll
    for (int a = 0; a < 4; a++)
        #pragma unroll
        for (int d = 0; d < 4; d++) acc[a][d] = 0.f;

    int Mact = g_Mact;
    int cl = tid >> 2, ql = tid & 3;           // Y loader mapping
    size_t ybase = ((size_t)b*CC + cl)*MP;
    __syncthreads();

    for (int j0 = 0; j0 < Mact; j0 += 32) {
        int jc = min(32, Mact - j0);
        __syncthreads();
        #pragma unroll
        for (int k = 0; k < 8; k++) {
            int j = ql*8 + k;
            float vr = 0.f, vi = 0.f;
            if (j < jc) { vr = g_Yr[ybase + j0 + j]; vi = g_Yi[ybase + j0 + j]; }
            yr[j][cl] = vr; yi[j][cl] = vi;
        }
        #pragma unroll
        for (int e = 0; e < 8; e++) {
            int idx = e*256 + tid;
            int nnb = idx >> 5, jj = idx & 31;
            float s, c;
            sincosf(zsm[nnb]*g_kcpt[j0+jj], &s, &c);
            float d = (zp[nnb]-g_ccpt[j0+jj])*g_iwcpt[j0+jj];
            float w = expf(-0.5f*d*d);
            cw[jj][nnb] = c*w;
            sw[jj][nnb] = s*w;
        }
        __syncthreads();
        #pragma unroll 2
        for (int j = 0; j < 32; j++) {
            float4 yrv = *(const float4*)&yr[j][ci*4];
            float4 yiv = *(const float4*)&yi[j][ci*4];
            float4 cwv = *(const float4*)&cw[j][ni*4];
            float4 swv = *(const float4*)&sw[j][ni*4];
            float yra[4] = {yrv.x, yrv.y, yrv.z, yrv.w};
            float yia[4] = {yiv.x, yiv.y, yiv.z, yiv.w};
            float cwa[4] = {cwv.x, cwv.y, cwv.z, cwv.w};
            float swa[4] = {swv.x, swv.y, swv.z, swv.w};
            #pragma unroll
            for (int a = 0; a < 4; a++)
                #pragma unroll
                for (int d = 0; d < 4; d++)
                    acc[a][d] = fmaf(yra[a], cwa[d], fmaf(-yia[a], swa[d], acc[a][d]));
        }
    }

    #pragma unroll
    for (int a = 0; a < 4; a++) {
        int c = ci*4 + a;
        float bv = bias[c];
        float4 o;
        o.x = acc[a][0]+bv; o.y = acc[a][1]+bv; o.z = acc[a][2]+bv; o.w = acc[a][3]+bv;
        *(float4*)(out + ((size_t)(b*CC + c))*NN + n0 + ni*4) = o;
    }
}

// ---------------- launch ----------------
extern "C" void kernel_launch(void* const* d_in, const int* in_sizes, int n_in,
                              void* d_out, int out_size)
{
    const float* x_feat          = (const float*)d_in[0];
    const float* z               = (const float*)d_in[1];
    const float* temb            = (const float*)d_in[2];
    const float* kappa_raw       = (const float*)d_in[3];
    const float* gabor_c         = (const float*)d_in[4];
    const float* gabor_omega_raw = (const float*)d_in[5];
    const float* wr              = (const float*)d_in[6];
    const float* wi              = (const float*)d_in[7];
    const float* bias            = (const float*)d_in[8];
    const float* tproj_w         = (const float*)d_in[9];
    const float* tproj_b         = (const float*)d_in[10];
    const float* mlp_w1          = (const float*)d_in[11];
    const float* mlp_b1          = (const float*)d_in[12];
    const float* mlp_w2          = (const float*)d_in[13];
    const float* mlp_b2          = (const float*)d_in[14];
    const float* tau0            = (const float*)d_in[15];
    const float* tau1            = (const float*)d_in[16];
    const float* alphar          = (const float*)d_in[17];
    const float* glow            = (const float*)d_in[18];
    const float* gmid            = (const float*)d_in[19];
    const float* ghigh           = (const float*)d_in[20];
    float* out = (float*)d_out;

    k_setup<<<1, 256>>>(temb, kappa_raw, gabor_c, gabor_omega_raw, tproj_w, tproj_b,
                        mlp_w1, mlp_b1, mlp_w2, mlp_b2, tau0, tau1, alphar,
                        glow, gmid, ghigh);
    dim3 g1((MM + 31)/32, NSPLIT, BB);     // (9, 16, 16); inactive m-tiles early-exit
    k_analysis<<<g1, 256>>>(x_feat, z);
    k_comb<<<BB*CC, MP>>>(wr, wi);
    dim3 g2(NN/64, BB);                    // (64, 16)
    k_synth<<<g2, 256>>>(z, bias, out);
}

// round 3
// speedup vs baseline: 3.6743x; 3.6743x over previous
#include <cuda_runtime.h>
#include <math.h>

#define BB 16
#define CC 64
#define NN 4096
#define KK 128
#define MM 257
#define TEMBD 256
#define HH 128
#define MP 288
#define NSPLIT 16
#define NS2 (NSPLIT*2)
#define PI_F 3.14159265358979323846f

// ---------------- device scratch ----------------
__device__ float g_tau[BB];
__device__ float g_gate[BB*MM];
__device__ float g_tvec[BB*CC];
__device__ int   g_midx[MP];
__device__ int   g_Mact;
__device__ float g_kcpt[MP];
__device__ float g_ccpt[MP];
__device__ float g_iwcpt[MP];
__device__ float g_Xr[(size_t)NS2*BB*CC*MP];
__device__ float g_Xi[(size_t)NS2*BB*CC*MP];
__device__ float g_Yr[(size_t)BB*CC*MP];
__device__ float g_Yi[(size_t)BB*CC*MP];

__device__ __forceinline__ float sigmoidf_(float x){ return 1.f/(1.f+expf(-x)); }
__device__ __forceinline__ float softplusf_(float x){ return log1pf(expf(x)); }

// ---------------- kernel A: per-batch MLP tau + tproj vec (16 blocks) ----------------
__global__ void __launch_bounds__(256) k_batch(const float* __restrict__ temb,
                                               const float* __restrict__ tproj_w,
                                               const float* __restrict__ tproj_b,
                                               const float* __restrict__ mlp_w1,
                                               const float* __restrict__ mlp_b1,
                                               const float* __restrict__ mlp_w2,
                                               const float* __restrict__ mlp_b2,
                                               const float* __restrict__ tau0p,
                                               const float* __restrict__ tau1p)
{
    int b = blockIdx.x;
    int tid = threadIdx.x;
    __shared__ float te[TEMBD], si[TEMBD];
    __shared__ float hid[HH];
    float v = temb[b*TEMBD + tid];
    te[tid] = v;
    si[tid] = v * sigmoidf_(v);
    __syncthreads();
    if (tid < HH) {
        float acc = mlp_b1[tid];
        const float* w = mlp_w1 + tid*TEMBD;
        #pragma unroll 8
        for (int t = 0; t < TEMBD; t++) acc = fmaf(te[t], w[t], acc);
        hid[tid] = acc * sigmoidf_(acc);
    } else if (tid < HH + CC) {
        int c = tid - HH;
        float acc = tproj_b[c];
        const float* w = tproj_w + c*TEMBD;
        #pragma unroll 8
        for (int t = 0; t < TEMBD; t++) acc = fmaf(si[t], w[t], acc);
        g_tvec[b*CC + c] = acc;
    }
    __syncthreads();
    if (tid == 0) {
        float acc = mlp_b2[0];
        for (int h = 0; h < HH; h++) acc = fmaf(hid[h], mlp_w2[h], acc);
        g_tau[b] = tau0p[0] + softplusf_(tau1p[0]) * tanhf(acc);
    }
}

// ---------------- kernel B: kappa, gates, compaction (1 block) ----------------
__global__ void __launch_bounds__(256) k_kappa(const float* __restrict__ kappa_raw,
                                               const float* __restrict__ gabor_c,
                                               const float* __restrict__ gabor_omega_raw,
                                               const float* __restrict__ alphap,
                                               const float* __restrict__ glowp,
                                               const float* __restrict__ gmidp,
                                               const float* __restrict__ ghighp)
{
    __shared__ float kpos[KK];
    __shared__ float kap[MM];
    __shared__ float gmax[MM];
    __shared__ float tau[BB];
    __shared__ float th1s, th2s;
    int tid = threadIdx.x;

    if (tid < KK) kpos[tid] = softplusf_(kappa_raw[tid]);
    if (tid < BB) tau[tid] = g_tau[tid];
    __syncthreads();
    if (tid == 0) {
        float s = 0.f;
        for (int k = 0; k < KK; k++) { s += kpos[k]; kpos[k] = s; }
        // sorted |kappa| = [0, kpos0,kpos0, kpos1,kpos1, ...], 257 values
        th1s = kpos[50]  + 0.4f*(kpos[51] - kpos[50]);
        th2s = kpos[101] + 0.8f*(kpos[102] - kpos[101]);
    }
    __syncthreads();

    float alpha = softplusf_(alphap[0]) + 1e-12f;
    float gl = sigmoidf_(glowp[0]);
    float gm = sigmoidf_(gmidp[0]);
    float gh = sigmoidf_(ghighp[0]);
    for (int m = tid; m < MM; m += blockDim.x) {
        float kv = (m < KK) ? -kpos[KK-1-m] : ((m == KK) ? 0.f : kpos[m-KK-1]);
        kap[m] = kv;
        float ka = fabsf(kv);
        float bandv = (ka <= th1s) ? gl : ((ka <= th2s) ? gm : gh);
        float mx = 0.f;
        for (int b = 0; b < BB; b++) {
            float g = bandv * sigmoidf_(alpha*(tau[b]-ka));
            g_gate[b*MM+m] = g;
            mx = fmaxf(mx, g);
        }
        gmax[m] = mx;
    }
    __syncthreads();

    if (tid == 0) {
        int cnt = 0;
        for (int m = 0; m < MM; m++) {
            if (gmax[m] > 1e-7f) {
                g_midx[cnt]  = m;
                g_kcpt[cnt]  = kap[m];
                g_ccpt[cnt]  = gabor_c[m];
                float om = fmaxf(softplusf_(gabor_omega_raw[m]), 1e-6f);
                g_iwcpt[cnt] = 1.f/om;
                cnt++;
            }
        }
        g_Mact = cnt;
        for (int j = cnt; j < MP; j++) { g_kcpt[j]=0.f; g_ccpt[j]=0.f; g_iwcpt[j]=1.f; g_midx[j]=0; }
    }
}

// ---------------- kernel 1: analysis ----------------
// block: 32 modes x 256 n x 64 c; thread tile 4c x 4m over an n-half (32 n per chunk-half)
__global__ void __launch_bounds__(256) k_analysis(const float* __restrict__ x_feat,
                                                  const float* __restrict__ z)
{
    int mt = blockIdx.x;
    int ns = blockIdx.y;
    int b  = blockIdx.z;
    int Mact = g_Mact;
    int m0 = mt * 32;
    if (m0 >= Mact) return;

    __shared__ float km[32], cm[32], iw[32];
    __shared__ float zs[64], zp[64];
    __shared__ float cwsm[64][32], swsm[64][32];
    __shared__ float xsm[64][68];

    int tid = threadIdx.x;
    if (tid < 32) {
        km[tid] = g_kcpt[m0+tid];
        cm[tid] = g_ccpt[m0+tid];
        iw[tid] = g_iwcpt[m0+tid];
    }
    int half = tid >> 7;
    int mg = tid & 7;
    int cg = (tid >> 3) & 15;
    float ar[4][4], ai[4][4];
    #pragma unroll
    for (int a = 0; a < 4; a++)
        #pragma unroll
        for (int k = 0; k < 4; k++) { ar[a][k] = 0.f; ai[a][k] = 0.f; }

    int c_tid = tid & 63, q_tid = tid >> 6;        // x loader: 64 c x 4 n-quarters
    float tvc = g_tvec[b*CC + c_tid];
    const float* zb = z + b*NN;

    for (int nc = 0; nc < 4; nc++) {
        int n0 = ns*256 + nc*64;
        __syncthreads();
        if (tid < 64) {
            float zv = zb[n0 + tid];
            zs[tid] = zv;
            zp[tid] = zv * (1.f/PI_F);
        }
        {
            const float4* xg = (const float4*)(x_feat + ((size_t)(b*CC + c_tid))*NN + n0);
            float4 v = xg[q_tid*4 + 0];
            int nn = q_tid*16;
            xsm[nn+0][c_tid]=v.x+tvc; xsm[nn+1][c_tid]=v.y+tvc; xsm[nn+2][c_tid]=v.z+tvc; xsm[nn+3][c_tid]=v.w+tvc;
            v = xg[q_tid*4 + 1];
            xsm[nn+4][c_tid]=v.x+tvc; xsm[nn+5][c_tid]=v.y+tvc; xsm[nn+6][c_tid]=v.z+tvc; xsm[nn+7][c_tid]=v.w+tvc;
            v = xg[q_tid*4 + 2];
            xsm[nn+8][c_tid]=v.x+tvc; xsm[nn+9][c_tid]=v.y+tvc; xsm[nn+10][c_tid]=v.z+tvc; xsm[nn+11][c_tid]=v.w+tvc;
            v = xg[q_tid*4 + 3];
            xsm[nn+12][c_tid]=v.x+tvc; xsm[nn+13][c_tid]=v.y+tvc; xsm[nn+14][c_tid]=v.z+tvc; xsm[nn+15][c_tid]=v.w+tvc;
        }
        __syncthreads();
        #pragma unroll
        for (int e = 0; e < 8; e++) {
            int idx = e*256 + tid;
            int nn = idx >> 5, mm = idx & 31;
            float s, c;
            __sincosf(zs[nn]*km[mm], &s, &c);
            float d = (zp[nn]-cm[mm])*iw[mm];
            float w = __expf(-0.5f*d*d);
            cwsm[nn][mm] = c*w;
            swsm[nn][mm] = s*w;
        }
        __syncthreads();
        int nbase = half*32;
        #pragma unroll 4
        for (int nn2 = 0; nn2 < 32; nn2++) {
            int nn = nbase + nn2;
            float4 xv = *(const float4*)&xsm[nn][cg*4];
            float4 cv = *(const float4*)&cwsm[nn][mg*4];
            float4 sv = *(const float4*)&swsm[nn][mg*4];
            float xa[4] = {xv.x, xv.y, xv.z, xv.w};
            float ca[4] = {cv.x, cv.y, cv.z, cv.w};
            float sa[4] = {sv.x, sv.y, sv.z, sv.w};
            #pragma unroll
            for (int a = 0; a < 4; a++)
                #pragma unroll
                for (int k = 0; k < 4; k++) {
                    ar[a][k] = fmaf(xa[a], ca[k], ar[a][k]);
                    ai[a][k] = fmaf(xa[a], sa[k], ai[a][k]);
                }
        }
    }

    int slot = ns*2 + half;
    size_t base = ((size_t)(slot*BB + b)*CC + cg*4)*MP + m0 + mg*4;
    #pragma unroll
    for (int a = 0; a < 4; a++) {
        float4 r; r.x=ar[a][0]; r.y=ar[a][1]; r.z=ar[a][2]; r.w=ar[a][3];
        float4 i; i.x=ai[a][0]; i.y=ai[a][1]; i.z=ai[a][2]; i.w=ai[a][3];
        *(float4*)&g_Xr[base + (size_t)a*MP] = r;
        *(float4*)&g_Xi[base + (size_t)a*MP] = i;
    }
}

// ---------------- kernel 2: combine splits, gate, complex weight (zero-pads Y) ----------------
__global__ void k_comb(const float* __restrict__ wr, const float* __restrict__ wi)
{
    int bc = blockIdx.x;
    int b = bc / CC, c = bc % CC;
    int j = threadIdx.x;
    size_t o = ((size_t)b*CC + c)*MP + j;
    if (j >= g_Mact) { g_Yr[o] = 0.f; g_Yi[o] = 0.f; return; }
    int m = g_midx[j];
    float xr = 0.f, xi = 0.f;
    #pragma unroll
    for (int ns = 0; ns < NS2; ns++) {
        size_t idx = ((size_t)(ns*BB + b)*CC + c)*MP + j;
        xr += g_Xr[idx];
        xi += g_Xi[idx];
    }
    xr *=  (1.f/(float)NN);
    xi *= -(1.f/(float)NN);
    float g = g_gate[b*MM+m];
    float wrv = wr[c*MM+m], wiv = wi[c*MM+m];
    g_Yr[o] = g*(xr*wrv - xi*wiv);
    g_Yi[o] = g*(xr*wiv + xi*wrv);
}

// ---------------- kernel 3: synthesis ----------------
// block: 128 n x 64 c, j-tiles of 16; thread tile 4c x 8n
__global__ void __launch_bounds__(256) k_synth(const float* __restrict__ z,
                                               const float* __restrict__ bias,
                                               float* __restrict__ out)
{
    int nt = blockIdx.x, b = blockIdx.y;
    int n0 = nt*128;
    __shared__ float zs[128], zp[128];
    __shared__ float yr[16][68], yi[16][68];
    __shared__ float cw[16][136], sw[16][136];
    int tid = threadIdx.x;
    if (tid < 128) {
        float zv = z[b*NN + n0 + tid];
        zs[tid] = zv;
        zp[tid] = zv*(1.f/PI_F);
    }
    int ni = tid & 15, ci = tid >> 4;
    float acc[4][8];
    #pragma unroll
    for (int a = 0; a < 4; a++)
        #pragma unroll
        for (int d = 0; d < 8; d++) acc[a][d] = 0.f;

    int Mact = g_Mact;
    int cl = tid >> 2, ql = tid & 3;
    size_t ybase = ((size_t)b*CC + cl)*MP;
    __syncthreads();

    for (int j0 = 0; j0 < Mact; j0 += 16) {
        __syncthreads();
        {
            float4 vr = *(const float4*)&g_Yr[ybase + j0 + ql*4];
            float4 vi = *(const float4*)&g_Yi[ybase + j0 + ql*4];
            yr[ql*4+0][cl]=vr.x; yr[ql*4+1][cl]=vr.y; yr[ql*4+2][cl]=vr.z; yr[ql*4+3][cl]=vr.w;
            yi[ql*4+0][cl]=vi.x; yi[ql*4+1][cl]=vi.y; yi[ql*4+2][cl]=vi.z; yi[ql*4+3][cl]=vi.w;
        }
        #pragma unroll
        for (int e = 0; e < 8; e++) {
            int idx = e*256 + tid;
            int jj = idx >> 7, nnb = idx & 127;
            float s, c;
            __sincosf(zs[nnb]*g_kcpt[j0+jj], &s, &c);
            float d = (zp[nnb]-g_ccpt[j0+jj])*g_iwcpt[j0+jj];
            float w = __expf(-0.5f*d*d);
            cw[jj][nnb] = c*w;
            sw[jj][nnb] = s*w;
        }
        __syncthreads();
        #pragma unroll 2
        for (int jj = 0; jj < 16; jj++) {
            float4 yrv = *(const float4*)&yr[jj][ci*4];
            float4 yiv = *(const float4*)&yi[jj][ci*4];
            float4 c0 = *(const float4*)&cw[jj][ni*8];
            float4 c1 = *(const float4*)&cw[jj][ni*8+4];
            float4 s0 = *(const float4*)&sw[jj][ni*8];
            float4 s1 = *(const float4*)&sw[jj][ni*8+4];
            float yra[4] = {yrv.x, yrv.y, yrv.z, yrv.w};
            float yia[4] = {yiv.x, yiv.y, yiv.z, yiv.w};
            float cwa[8] = {c0.x,c0.y,c0.z,c0.w,c1.x,c1.y,c1.z,c1.w};
            float swa[8] = {s0.x,s0.y,s0.z,s0.w,s1.x,s1.y,s1.z,s1.w};
            #pragma unroll
            for (int a = 0; a < 4; a++)
                #pragma unroll
                for (int d = 0; d < 8; d++)
                    acc[a][d] = fmaf(yra[a], cwa[d], fmaf(-yia[a], swa[d], acc[a][d]));
        }
    }

    #pragma unroll
    for (int a = 0; a < 4; a++) {
        int c = ci*4 + a;
        float bv = bias[c];
        float4 o0, o1;
        o0.x = acc[a][0]+bv; o0.y = acc[a][1]+bv; o0.z = acc[a][2]+bv; o0.w = acc[a][3]+bv;
        o1.x = acc[a][4]+bv; o1.y = acc[a][5]+bv; o1.z = acc[a][6]+bv; o1.w = acc[a][7]+bv;
        float* op = out + ((size_t)(b*CC + c))*NN + n0 + ni*8;
        *(float4*)op = o0;
        *(float4*)(op+4) = o1;
    }
}

// ---------------- launch ----------------
extern "C" void kernel_launch(void* const* d_in, const int* in_sizes, int n_in,
                              void* d_out, int out_size)
{
    const float* x_feat          = (const float*)d_in[0];
    const float* z               = (const float*)d_in[1];
    const float* temb            = (const float*)d_in[2];
    const float* kappa_raw       = (const float*)d_in[3];
    const float* gabor_c         = (const float*)d_in[4];
    const float* gabor_omega_raw = (const float*)d_in[5];
    const float* wr              = (const float*)d_in[6];
    const float* wi              = (const float*)d_in[7];
    const float* bias            = (const float*)d_in[8];
    const float* tproj_w         = (const float*)d_in[9];
    const float* tproj_b         = (const float*)d_in[10];
    const float* mlp_w1          = (const float*)d_in[11];
    const float* mlp_b1          = (const float*)d_in[12];
    const float* mlp_w2          = (const float*)d_in[13];
    const float* mlp_b2          = (const float*)d_in[14];
    const float* tau0            = (const float*)d_in[15];
    const float* tau1            = (const float*)d_in[16];
    const float* alphar          = (const float*)d_in[17];
    const float* glow            = (const float*)d_in[18];
    const float* gmid            = (const float*)d_in[19];
    const float* ghigh           = (const float*)d_in[20];
    float* out = (float*)d_out;

    k_batch<<<BB, 256>>>(temb, tproj_w, tproj_b, mlp_w1, mlp_b1, mlp_w2, mlp_b2, tau0, tau1);
    k_kappa<<<1, 256>>>(kappa_raw, gabor_c, gabor_omega_raw, alphar, glow, gmid, ghigh);
    dim3 g1((MM + 31)/32, NSPLIT, BB);     // (9, 16, 16); inactive m-tiles early-exit
    k_analysis<<<g1, 256>>>(x_feat, z);
    k_comb<<<BB*CC, MP>>>(wr, wi);
    dim3 g2(NN/128, BB);                   // (32, 16)
    k_synth<<<g2, 256>>>(z, bias, out);
}